// round 15
// baseline (speedup 1.0000x reference)
#include <cuda_runtime.h>
#include <cuda_fp16.h>

#define NA 50000
#define NM 50000
#define NI 600000
#define NG 512
#define H 64
#define MD 94
#define HOUT 128
#define KA 96             // attr K padded (94 -> 96)
#define NZ 101
#define BN_EPS 1e-5f
#define SCAN_BLOCKS 196   // ceil(50000/256)
#define NGRP (NI / 16)    // 37500

// ---------------- device scratch ----------------
__device__ __align__(256) float d_Tf[NZ * H];
__device__ __align__(256) float d_Tc[NZ * H];
__device__ __align__(256) float d_U[NZ * 128];    // emb @ W[64:128] (f|c halves)
__device__ __align__(256) float d_Mf[NM * H];     // fp32 (gemm -> hxw2 only)
__device__ __align__(256) float d_Mc[NM * H];
__device__ __align__(256) __half d_Mfh[NM * H];   // fp16 operands for k_msg
__device__ __align__(256) __half d_Mch[NM * H];
__device__ __align__(256) float d_osum[NA * H];
__device__ float d_bnsum[H];
__device__ float d_bnsq[H];
__device__ __align__(256) float d_gsum[NG * H];
__device__ float d_gcnt[NG];
// sort machinery (both sides)
__device__ int d_icnt_s[NA];
__device__ int d_icnt_h[NM];
__device__ int d_off_s[NA + 1];
__device__ int d_off_h[NM + 1];
__device__ int d_cur_s[NA];
__device__ int d_cur_h[NM];
__device__ int d_bsum[2][256];    // padded to 256 (tail zero)
__device__ float d_rcs[NA];
__device__ float d_rch[NM];
__device__ __align__(16) unsigned short d_zA[NI];  // atom TYPE per incidence, hid-sorted
__device__ __align__(16) unsigned d_sB[NI];        // (h<<16)|s per incidence, src-sorted

// ---------------- fast math ----------------
__device__ __forceinline__ float ex2f(float x) { float r; asm("ex2.approx.ftz.f32 %0,%1;" : "=f"(r) : "f"(x)); return r; }
__device__ __forceinline__ float lg2f(float x) { float r; asm("lg2.approx.ftz.f32 %0,%1;" : "=f"(r) : "f"(x)); return r; }
__device__ __forceinline__ float rcpf(float x) { float r; asm("rcp.approx.ftz.f32 %0,%1;" : "=f"(r) : "f"(x)); return r; }
__device__ __forceinline__ float tanhf_a(float x) { float r; asm("tanh.approx.f32 %0,%1;" : "=f"(r) : "f"(x)); return r; }

#define L2E 1.4426950408889634f
#define LN2 0.6931471805599453f

// gate = sigmoid(a) * softplus(b); sigmoid via tanh.approx (3 MUFU total)
__device__ __forceinline__ float gatef(float a, float b) {
    float sg = fmaf(0.5f, tanhf_a(0.5f * a), 0.5f);
    float sp = lg2f(1.0f + ex2f(b * L2E)) * LN2;
    return sg * sp;
}

__device__ __forceinline__ void red_add_v4(float* p, float4 v) {
    asm volatile("red.global.add.v4.f32 [%0], {%1,%2,%3,%4};"
                 :: "l"(p), "f"(v.x), "f"(v.y), "f"(v.z), "f"(v.w) : "memory");
}
__device__ __forceinline__ void red_add_1(float* p, float v) {
    asm volatile("red.global.add.f32 [%0], %1;" :: "l"(p), "f"(v) : "memory");
}

// unpack 4 halves (8 B) -> float4
__device__ __forceinline__ float4 ld_half4(const __half* p) {
    uint2 u = __ldg((const uint2*)p);
    __half2 h0 = *reinterpret_cast<__half2*>(&u.x);
    __half2 h1 = *reinterpret_cast<__half2*>(&u.y);
    float2 f0 = __half22float2(h0);
    float2 f1 = __half22float2(h1);
    return make_float4(f0.x, f0.y, f1.x, f1.y);
}

// ---------------- kernels ----------------
__global__ void k_zero() {
    int tid = blockIdx.x * blockDim.x + threadIdx.x;
    int stride = gridDim.x * blockDim.x;
    for (int i = tid; i < NA * H; i += stride) d_osum[i] = 0.f;
    for (int i = tid; i < NA; i += stride) d_icnt_s[i] = 0;
    for (int i = tid; i < NM; i += stride) d_icnt_h[i] = 0;
    for (int i = tid; i < NG * H; i += stride) d_gsum[i] = 0.f;
    if (tid < NG) d_gcnt[tid] = 0.f;
    if (tid < H) { d_bnsum[tid] = 0.f; d_bnsq[tid] = 0.f; }
    if (tid < 256) { d_bsum[0][tid] = 0; d_bsum[1][tid] = 0; }
    if (tid == 0) { d_off_s[NA] = NI; d_off_h[NM] = NI; }
}

// tables: Tf/Tc = emb@W[:64] halves; U = emb@W[64:128] halves (101 x 128)
__global__ __launch_bounds__(256) void k_tables(const float* __restrict__ emb,
                                                const float* __restrict__ w_f,
                                                const float* __restrict__ w_c) {
    __shared__ float e[H];
    int z = blockIdx.x;
    int t = threadIdx.x;
    if (t < H) e[t] = emb[z * H + t];
    __syncthreads();
    float acc = 0.f;
    if (t < 64) {
#pragma unroll 8
        for (int k = 0; k < H; k++) acc = fmaf(e[k], w_f[k * H + t], acc);
        d_Tf[z * H + t] = acc;
    } else if (t < 128) {
        int j = t - 64;
#pragma unroll 8
        for (int k = 0; k < H; k++) acc = fmaf(e[k], w_c[k * H + j], acc);
        d_Tc[z * H + j] = acc;
    } else if (t < 192) {
        int j = t - 128;
#pragma unroll 8
        for (int k = 0; k < H; k++) acc = fmaf(e[k], w_f[(64 + k) * H + j], acc);
        d_U[z * 128 + j] = acc;
    } else {
        int j = t - 192;
#pragma unroll 8
        for (int k = 0; k < H; k++) acc = fmaf(e[k], w_c[(64 + k) * H + j], acc);
        d_U[z * 128 + 64 + j] = acc;
    }
}

__global__ void k_counts(const int* __restrict__ src, const int* __restrict__ hid,
                         const int* __restrict__ batch) {
    int e = blockIdx.x * blockDim.x + threadIdx.x;
    if (e < NI) {
        atomicAdd(&d_icnt_s[src[e]], 1);
        atomicAdd(&d_icnt_h[hid[e]], 1);
    }
    if (e < NA) red_add_1(&d_gcnt[batch[e]], 1.0f);
}

// pass 1: per-block inclusive scan, write local-exclusive offs + block sums
__global__ __launch_bounds__(256) void k_scan1() {
    __shared__ int sh[256];
    int side = blockIdx.y;
    const int* cnt = side ? d_icnt_h : d_icnt_s;
    int* off = side ? d_off_h : d_off_s;
    int t = threadIdx.x;
    int i = blockIdx.x * 256 + t;
    int v = (i < NA) ? cnt[i] : 0;
    sh[t] = v;
    __syncthreads();
#pragma unroll
    for (int d = 1; d < 256; d <<= 1) {
        int u = (t >= d) ? sh[t - d] : 0;
        __syncthreads();
        sh[t] += u;
        __syncthreads();
    }
    if (i < NA) off[i] = sh[t] - v;
    if (t == 255) d_bsum[side][blockIdx.x] = sh[255];
}

// pass 2+3 fused: each block re-scans block sums locally, applies offset
__global__ __launch_bounds__(256) void k_scan23() {
    __shared__ int sh[256];
    int side = blockIdx.y;
    int t = threadIdx.x;
    int v = d_bsum[side][t];
    sh[t] = v;
    __syncthreads();
#pragma unroll
    for (int d = 1; d < 256; d <<= 1) {
        int u = (t >= d) ? sh[t - d] : 0;
        __syncthreads();
        sh[t] += u;
        __syncthreads();
    }
    int boff = sh[blockIdx.x] - d_bsum[side][blockIdx.x];  // exclusive
    int i = blockIdx.x * 256 + t;
    if (i >= NA) return;
    if (side == 0) {
        int o = d_off_s[i] + boff;
        d_off_s[i] = o;
        d_cur_s[i] = o;
        d_rcs[i] = __fdividef(1.0f, fmaxf((float)d_icnt_s[i], 1.0f));
    } else {
        int o = d_off_h[i] + boff;
        d_off_h[i] = o;
        d_cur_h[i] = o;
        d_rch[i] = __fdividef(1.0f, fmaxf((float)d_icnt_h[i], 1.0f));
    }
}

__global__ void k_sort(const int* __restrict__ src, const int* __restrict__ hid,
                       const int* __restrict__ az) {
    int e = blockIdx.x * blockDim.x + threadIdx.x;
    if (e >= NI) return;
    int s = src[e];
    int h = hid[e];
    int z = __ldg(az + s);
    int ph = atomicAdd(&d_cur_h[h], 1);
    d_zA[ph] = (unsigned short)z;
    int ps = atomicAdd(&d_cur_s[s], 1);
    d_sB[ps] = ((unsigned)h << 16) | (unsigned)s;
}

// motif GEMM (attr only, K=96): [Mf|Mc] = attr @ W[128:222] + bias  (fork stream)
__global__ __launch_bounds__(256) void k_gemm_attr(const float* __restrict__ w_f,
                                                   const float* __restrict__ w_c,
                                                   const float* __restrict__ b_f,
                                                   const float* __restrict__ b_c,
                                                   const float* __restrict__ attr) {
    __shared__ float Wsm[KA * 128];   // 48 KB
    __shared__ float Xsm[64 * KA];    // 24 KB
    int t = threadIdx.x;
    int tx = t & 31;
    int ry = t >> 5;

    for (int idx = t; idx < KA * 128; idx += 256) {
        int k = idx >> 7, j = idx & 127;
        float v = 0.f;
        if (k < MD) v = (j < 64) ? w_f[(128 + k) * H + j] : w_c[(128 + k) * H + j - 64];
        Wsm[idx] = v;
    }
    int row0 = blockIdx.x * 64;
    for (int idx = t; idx < 64 * KA; idx += 256) {
        int r = idx / KA;
        int k = idx - r * KA;
        int row = row0 + r;
        float v = 0.f;
        if (row < NM && k < MD) v = attr[row * MD + k];
        Xsm[idx] = v;
    }
    __syncthreads();

    float acc[8][4];
#pragma unroll
    for (int r = 0; r < 8; r++)
#pragma unroll
        for (int c = 0; c < 4; c++) acc[r][c] = 0.f;

    for (int k0 = 0; k0 < KA; k0 += 4) {
        float4 wv[4];
#pragma unroll
        for (int i = 0; i < 4; i++)
            wv[i] = *reinterpret_cast<const float4*>(&Wsm[(k0 + i) * 128 + tx * 4]);
#pragma unroll
        for (int r = 0; r < 8; r++) {
            float4 xv = *reinterpret_cast<const float4*>(&Xsm[(ry * 8 + r) * KA + k0]);
            acc[r][0] = fmaf(xv.x, wv[0].x, acc[r][0]);
            acc[r][1] = fmaf(xv.x, wv[0].y, acc[r][1]);
            acc[r][2] = fmaf(xv.x, wv[0].z, acc[r][2]);
            acc[r][3] = fmaf(xv.x, wv[0].w, acc[r][3]);
            acc[r][0] = fmaf(xv.y, wv[1].x, acc[r][0]);
            acc[r][1] = fmaf(xv.y, wv[1].y, acc[r][1]);
            acc[r][2] = fmaf(xv.y, wv[1].z, acc[r][2]);
            acc[r][3] = fmaf(xv.y, wv[1].w, acc[r][3]);
            acc[r][0] = fmaf(xv.z, wv[2].x, acc[r][0]);
            acc[r][1] = fmaf(xv.z, wv[2].y, acc[r][1]);
            acc[r][2] = fmaf(xv.z, wv[2].z, acc[r][2]);
            acc[r][3] = fmaf(xv.z, wv[2].w, acc[r][3]);
            acc[r][0] = fmaf(xv.w, wv[3].x, acc[r][0]);
            acc[r][1] = fmaf(xv.w, wv[3].y, acc[r][1]);
            acc[r][2] = fmaf(xv.w, wv[3].z, acc[r][2]);
            acc[r][3] = fmaf(xv.w, wv[3].w, acc[r][3]);
        }
    }

    int col = tx * 4;
    float4 bias;
    if (col < 64) bias = *reinterpret_cast<const float4*>(&b_f[col]);
    else          bias = *reinterpret_cast<const float4*>(&b_c[col - 64]);
#pragma unroll
    for (int r = 0; r < 8; r++) {
        int row = row0 + ry * 8 + r;
        if (row < NM) {
            float4 o;
            o.x = acc[r][0] + bias.x; o.y = acc[r][1] + bias.y;
            o.z = acc[r][2] + bias.z; o.w = acc[r][3] + bias.w;
            if (col < 64) *reinterpret_cast<float4*>(&d_Mf[row * H + col]) = o;
            else          *reinterpret_cast<float4*>(&d_Mc[row * H + col - 64]) = o;
        }
    }
}

// phase A (after join): M = Mf/Mc(fp32) + (segment-sum of U[z]) * rch,
// emitted as fp16 operand arrays for k_msg (single rounding).
__global__ __launch_bounds__(256) void k_hxw2() {
    int m = blockIdx.x * 8 + (threadIdx.x >> 5);
    if (m >= NM) return;
    int q = (threadIdx.x & 31) << 2;
    int b = d_off_h[m], e = d_off_h[m + 1];
    float4 acc = make_float4(0.f, 0.f, 0.f, 0.f);
    int j = b;
    for (; j + 3 < e; j += 4) {
        int z0 = __ldg(d_zA + j), z1 = __ldg(d_zA + j + 1);
        int z2 = __ldg(d_zA + j + 2), z3 = __ldg(d_zA + j + 3);
        float4 v0 = __ldg((const float4*)(d_U + z0 * 128 + q));
        float4 v1 = __ldg((const float4*)(d_U + z1 * 128 + q));
        float4 v2 = __ldg((const float4*)(d_U + z2 * 128 + q));
        float4 v3 = __ldg((const float4*)(d_U + z3 * 128 + q));
        acc.x += (v0.x + v1.x) + (v2.x + v3.x);
        acc.y += (v0.y + v1.y) + (v2.y + v3.y);
        acc.z += (v0.z + v1.z) + (v2.z + v3.z);
        acc.w += (v0.w + v1.w) + (v2.w + v3.w);
    }
    for (; j < e; j++) {
        int z = __ldg(d_zA + j);
        float4 v = __ldg((const float4*)(d_U + z * 128 + q));
        acc.x += v.x; acc.y += v.y; acc.z += v.z; acc.w += v.w;
    }
    float rc = d_rch[m];
    const float* srcp = (q < 64) ? (d_Mf + m * H + q) : (d_Mc + m * H + (q - 64));
    __half* dsth = (q < 64) ? (d_Mfh + m * H + q) : (d_Mch + m * H + (q - 64));
    float4 o = *reinterpret_cast<const float4*>(srcp);
    o.x += acc.x * rc; o.y += acc.y * rc;
    o.z += acc.z * rc; o.w += acc.w * rc;
    __half2 p0 = __floats2half2_rn(o.x, o.y);
    __half2 p1 = __floats2half2_rn(o.z, o.w);
    uint2 u;
    u.x = *reinterpret_cast<unsigned*>(&p0);
    u.y = *reinterpret_cast<unsigned*>(&p1);
    *reinterpret_cast<uint2*>(dsth) = u;
}

// phase B: src-sorted chunks of 16; fp16 operand gather (half the L2 bytes);
// run-length register accumulation, red.v4 flush on atom change.
__global__ __launch_bounds__(256) void k_msg(const int* __restrict__ az) {
    int t = threadIdx.x;
    int grp = blockIdx.x * 16 + (t >> 4);
    if (grp >= NGRP) return;
    int q = (t & 15) << 2;
    int B = grp * 16;

    uint4 R[4];
#pragma unroll
    for (int i = 0; i < 4; i++)
        R[i] = __ldg((const uint4*)(d_sB + B + i * 4));

    int cur = -1;
    float4 acc = make_float4(0.f, 0.f, 0.f, 0.f);
    float4 tf = acc, tc = acc;

#pragma unroll
    for (int i0 = 0; i0 < 4; i0++) {
        unsigned rr[4] = {R[i0].x, R[i0].y, R[i0].z, R[i0].w};
        float4 mf[4], mc[4];
#pragma unroll
        for (int j = 0; j < 4; j++) {
            int m = (int)(rr[j] >> 16);
            mf[j] = ld_half4(d_Mfh + m * H + q);
            mc[j] = ld_half4(d_Mch + m * H + q);
        }
#pragma unroll
        for (int j = 0; j < 4; j++) {
            int s = (int)(rr[j] & 0xFFFFu);
            if (s != cur) {
                if (cur >= 0) red_add_v4(&d_osum[cur * H + q], acc);
                cur = s;
                acc = make_float4(0.f, 0.f, 0.f, 0.f);
                int z = __ldg(az + s);
                tf = __ldg((const float4*)(d_Tf + z * H + q));
                tc = __ldg((const float4*)(d_Tc + z * H + q));
            }
            acc.x += gatef(tf.x + mf[j].x, tc.x + mc[j].x);
            acc.y += gatef(tf.y + mf[j].y, tc.y + mc[j].y);
            acc.z += gatef(tf.z + mf[j].z, tc.z + mc[j].z);
            acc.w += gatef(tf.w + mf[j].w, tc.w + mc[j].w);
        }
    }
    red_add_v4(&d_osum[cur * H + q], acc);
}

// BN statistics over out = osum * rcs
__global__ __launch_bounds__(256) void k_bnstats() {
    __shared__ float b1[64], b2[64];
    int t = threadIdx.x;
    if (t < 64) { b1[t] = 0.f; b2[t] = 0.f; }
    __syncthreads();
    int start = blockIdx.x * 256 + t;
    int q = (start & 15) << 2;
    float l1[4] = {0.f, 0.f, 0.f, 0.f};
    float l2[4] = {0.f, 0.f, 0.f, 0.f};
    for (int idx = start; idx < NA * 16; idx += 65536) {
        int i = idx >> 4;
        float rc = d_rcs[i];
        float4 o = *reinterpret_cast<const float4*>(&d_osum[i * H + q]);
        o.x *= rc; o.y *= rc; o.z *= rc; o.w *= rc;
        l1[0] += o.x; l2[0] += o.x * o.x;
        l1[1] += o.y; l2[1] += o.y * o.y;
        l1[2] += o.z; l2[2] += o.z * o.z;
        l1[3] += o.w; l2[3] += o.w * o.w;
    }
#pragma unroll
    for (int c = 0; c < 4; c++) {
        atomicAdd(&b1[q + c], l1[c]);
        atomicAdd(&b2[q + c], l2[c]);
    }
    __syncthreads();
    if (t < 64) {
        red_add_1(&d_bnsum[t], b1[t]);
        red_add_1(&d_bnsq[t], b2[t]);
    }
}

// normalize + residual + relu + pool
__global__ void k_final(const int* __restrict__ batch, const float* __restrict__ gamma,
                        const float* __restrict__ beta, const int* __restrict__ az,
                        const float* __restrict__ emb) {
    int tid = blockIdx.x * blockDim.x + threadIdx.x;
    if (tid >= NA * 16) return;
    int i = tid >> 4;
    int q = (tid & 15) << 2;
    int z = __ldg(az + i);
    float rc = d_rcs[i];
    float4 o = *reinterpret_cast<const float4*>(&d_osum[i * H + q]);
    float4 xv = __ldg((const float4*)(emb + z * H + q));
    float ov[4] = {o.x * rc, o.y * rc, o.z * rc, o.w * rc};
    float xr[4] = {xv.x, xv.y, xv.z, xv.w};
    float res[4];
#pragma unroll
    for (int c = 0; c < 4; c++) {
        int f = q + c;
        float mu = d_bnsum[f] * (1.0f / NA);
        float var = d_bnsq[f] * (1.0f / NA) - mu * mu;
        float inv = rsqrtf(var + BN_EPS);
        float v = (ov[c] - mu) * inv * gamma[f] + beta[f] + xr[c];
        res[c] = fmaxf(v, 0.f);
    }
    float4 r; r.x = res[0]; r.y = res[1]; r.z = res[2]; r.w = res[3];
    int g = __ldg(batch + i);
    red_add_v4(&d_gsum[g * H + q], r);
}

// MLP head (exact softplus kept here — 512 values only)
__global__ __launch_bounds__(128) void k_head(const float* __restrict__ w_l1,
                                              const float* __restrict__ b_l1,
                                              const float* __restrict__ w_out,
                                              const float* __restrict__ b_out,
                                              float* __restrict__ out) {
    __shared__ float gsm[64];
    __shared__ float red[128];
    int g = blockIdx.x;
    int t = threadIdx.x;
    if (t < 64) gsm[t] = d_gsum[g * H + t] * __fdividef(1.0f, fmaxf(d_gcnt[g], 1.0f));
    __syncthreads();
    float acc = b_l1[t];
#pragma unroll
    for (int f = 0; f < 64; f++)
        acc = fmaf(gsm[f], w_l1[f * HOUT + t], acc);
    float sp = lg2f(1.0f + ex2f(acc * L2E)) * LN2;
    red[t] = sp * w_out[t];
    __syncthreads();
    if (t < 64) red[t] += red[t + 64];
    __syncthreads();
    if (t < 32) {
        float s = red[t] + red[t + 32];
#pragma unroll
        for (int off = 16; off > 0; off >>= 1)
            s += __shfl_down_sync(0xffffffff, s, off);
        if (t == 0) out[g] = s + b_out[0];
    }
}

// ---------------- launch ----------------
extern "C" void kernel_launch(void* const* d_in, const int* in_sizes, int n_in,
                              void* d_out_p, int out_size) {
    const int*   atom_z = (const int*)d_in[0];
    const float* attr   = (const float*)d_in[1];
    const int*   hei    = (const int*)d_in[2];
    const int*   batch  = (const int*)d_in[3];
    const float* emb    = (const float*)d_in[4];
    const float* w_f    = (const float*)d_in[5];
    const float* b_f    = (const float*)d_in[6];
    const float* w_c    = (const float*)d_in[7];
    const float* b_c    = (const float*)d_in[8];
    const float* gamma  = (const float*)d_in[9];
    const float* beta   = (const float*)d_in[10];
    const float* w_l1   = (const float*)d_in[11];
    const float* b_l1   = (const float*)d_in[12];
    const float* w_out  = (const float*)d_in[13];
    const float* b_out  = (const float*)d_in[14];
    float* out = (float*)d_out_p;

    const int* src = hei;
    const int* hid = hei + NI;

    // Single auxiliary stream + 2 events (guard-proven R8 configuration).
    cudaStream_t s2;
    cudaEvent_t evF, evJ;
    cudaStreamCreateWithFlags(&s2, cudaStreamNonBlocking);
    cudaEventCreateWithFlags(&evF, cudaEventDisableTiming);
    cudaEventCreateWithFlags(&evJ, cudaEventDisableTiming);

    cudaEventRecord(evF, 0);
    cudaStreamWaitEvent(s2, evF, 0);
    k_tables<<<NZ, 256, 0, s2>>>(emb, w_f, w_c);
    k_gemm_attr<<<(NM + 63) / 64, 256, 0, s2>>>(w_f, w_c, b_f, b_c, attr);
    cudaEventRecord(evJ, s2);

    // origin: zero -> counts -> scan -> sort (exact R8 chain)
    k_zero<<<512, 256>>>();
    k_counts<<<(NI + 255) / 256, 256>>>(src, hid, batch);
    k_scan1<<<dim3(SCAN_BLOCKS, 2), 256>>>();
    k_scan23<<<dim3(SCAN_BLOCKS, 2), 256>>>();
    k_sort<<<(NI + 255) / 256, 256>>>(src, hid, atom_z);

    cudaStreamWaitEvent(0, evJ, 0);   // join: Mf/Mc + U ready
    k_hxw2<<<(NM + 7) / 8, 256>>>();
    k_msg<<<(NGRP + 15) / 16, 256>>>(atom_z);
    k_bnstats<<<256, 256>>>();
    k_final<<<(NA * 16 + 255) / 256, 256>>>(batch, gamma, beta, atom_z, emb);
    k_head<<<NG, 128>>>(w_l1, b_l1, w_out, b_out, out);
}

// round 16
// speedup vs baseline: 1.0157x; 1.0157x over previous
#include <cuda_runtime.h>

#define NA 50000
#define NM 50000
#define NI 600000
#define NG 512
#define H 64
#define MD 94
#define HOUT 128
#define KA 96             // attr K padded (94 -> 96)
#define NZ 101
#define BN_EPS 1e-5f
#define SCAN_BLOCKS 196   // ceil(50000/256)
#define CH 32             // incidences per 16-thread group in k_msg
#define NGRP (NI / CH)    // 18750

// ---------------- device scratch ----------------
__device__ __align__(256) float d_Tf[NZ * H];
__device__ __align__(256) float d_Tc[NZ * H];
__device__ __align__(256) float d_U[NZ * 128];    // emb @ W[64:128] (f|c halves)
__device__ __align__(256) float d_Mf[NM * H];
__device__ __align__(256) float d_Mc[NM * H];
__device__ __align__(256) float d_osum[NA * H];
__device__ float d_bnsum[H];
__device__ float d_bnsq[H];
__device__ __align__(256) float d_gsum[NG * H];
__device__ float d_gcnt[NG];
// sort machinery (both sides)
__device__ int d_icnt_s[NA];
__device__ int d_icnt_h[NM];
__device__ int d_off_s[NA + 1];
__device__ int d_off_h[NM + 1];
__device__ int d_cur_s[NA];
__device__ int d_cur_h[NM];
__device__ int d_bsum[2][256];    // padded to 256 (tail zero)
__device__ float d_rcs[NA];
__device__ float d_rch[NM];
__device__ __align__(16) unsigned short d_zA[NI];  // atom TYPE per incidence, hid-sorted
__device__ __align__(16) unsigned d_sB[NI];        // (h<<16)|s per incidence, src-sorted

// ---------------- fast math ----------------
__device__ __forceinline__ float ex2f(float x) { float r; asm("ex2.approx.ftz.f32 %0,%1;" : "=f"(r) : "f"(x)); return r; }
__device__ __forceinline__ float lg2f(float x) { float r; asm("lg2.approx.ftz.f32 %0,%1;" : "=f"(r) : "f"(x)); return r; }
__device__ __forceinline__ float rcpf(float x) { float r; asm("rcp.approx.ftz.f32 %0,%1;" : "=f"(r) : "f"(x)); return r; }
__device__ __forceinline__ float tanhf_a(float x) { float r; asm("tanh.approx.f32 %0,%1;" : "=f"(r) : "f"(x)); return r; }

#define L2E 1.4426950408889634f
#define LN2 0.6931471805599453f

// gate = sigmoid(a) * softplus(b); sigmoid via tanh.approx (3 MUFU total)
__device__ __forceinline__ float gatef(float a, float b) {
    float sg = fmaf(0.5f, tanhf_a(0.5f * a), 0.5f);
    float sp = lg2f(1.0f + ex2f(b * L2E)) * LN2;
    return sg * sp;
}

__device__ __forceinline__ void red_add_v4(float* p, float4 v) {
    asm volatile("red.global.add.v4.f32 [%0], {%1,%2,%3,%4};"
                 :: "l"(p), "f"(v.x), "f"(v.y), "f"(v.z), "f"(v.w) : "memory");
}
__device__ __forceinline__ void red_add_1(float* p, float v) {
    asm volatile("red.global.add.f32 [%0], %1;" :: "l"(p), "f"(v) : "memory");
}

// ---------------- kernels ----------------
__global__ void k_zero() {
    int tid = blockIdx.x * blockDim.x + threadIdx.x;
    int stride = gridDim.x * blockDim.x;
    for (int i = tid; i < NA * H; i += stride) d_osum[i] = 0.f;
    for (int i = tid; i < NA; i += stride) d_icnt_s[i] = 0;
    for (int i = tid; i < NM; i += stride) d_icnt_h[i] = 0;
    for (int i = tid; i < NG * H; i += stride) d_gsum[i] = 0.f;
    if (tid < NG) d_gcnt[tid] = 0.f;
    if (tid < H) { d_bnsum[tid] = 0.f; d_bnsq[tid] = 0.f; }
    if (tid < 256) { d_bsum[0][tid] = 0; d_bsum[1][tid] = 0; }
    if (tid == 0) { d_off_s[NA] = NI; d_off_h[NM] = NI; }
}

// tables: Tf/Tc = emb@W[:64] halves; U = emb@W[64:128] halves (101 x 128)
__global__ __launch_bounds__(256) void k_tables(const float* __restrict__ emb,
                                                const float* __restrict__ w_f,
                                                const float* __restrict__ w_c) {
    __shared__ float e[H];
    int z = blockIdx.x;
    int t = threadIdx.x;
    if (t < H) e[t] = emb[z * H + t];
    __syncthreads();
    float acc = 0.f;
    if (t < 64) {
#pragma unroll 8
        for (int k = 0; k < H; k++) acc = fmaf(e[k], w_f[k * H + t], acc);
        d_Tf[z * H + t] = acc;
    } else if (t < 128) {
        int j = t - 64;
#pragma unroll 8
        for (int k = 0; k < H; k++) acc = fmaf(e[k], w_c[k * H + j], acc);
        d_Tc[z * H + j] = acc;
    } else if (t < 192) {
        int j = t - 128;
#pragma unroll 8
        for (int k = 0; k < H; k++) acc = fmaf(e[k], w_f[(64 + k) * H + j], acc);
        d_U[z * 128 + j] = acc;
    } else {
        int j = t - 192;
#pragma unroll 8
        for (int k = 0; k < H; k++) acc = fmaf(e[k], w_c[(64 + k) * H + j], acc);
        d_U[z * 128 + 64 + j] = acc;
    }
}

__global__ void k_counts(const int* __restrict__ src, const int* __restrict__ hid,
                         const int* __restrict__ batch) {
    int e = blockIdx.x * blockDim.x + threadIdx.x;
    if (e < NI) {
        atomicAdd(&d_icnt_s[src[e]], 1);
        atomicAdd(&d_icnt_h[hid[e]], 1);
    }
    if (e < NA) red_add_1(&d_gcnt[batch[e]], 1.0f);
}

// pass 1: per-block inclusive scan, write local-exclusive offs + block sums
__global__ __launch_bounds__(256) void k_scan1() {
    __shared__ int sh[256];
    int side = blockIdx.y;
    const int* cnt = side ? d_icnt_h : d_icnt_s;
    int* off = side ? d_off_h : d_off_s;
    int t = threadIdx.x;
    int i = blockIdx.x * 256 + t;
    int v = (i < NA) ? cnt[i] : 0;
    sh[t] = v;
    __syncthreads();
#pragma unroll
    for (int d = 1; d < 256; d <<= 1) {
        int u = (t >= d) ? sh[t - d] : 0;
        __syncthreads();
        sh[t] += u;
        __syncthreads();
    }
    if (i < NA) off[i] = sh[t] - v;
    if (t == 255) d_bsum[side][blockIdx.x] = sh[255];
}

// pass 2+3 fused: each block re-scans block sums locally, applies offset
__global__ __launch_bounds__(256) void k_scan23() {
    __shared__ int sh[256];
    int side = blockIdx.y;
    int t = threadIdx.x;
    int v = d_bsum[side][t];
    sh[t] = v;
    __syncthreads();
#pragma unroll
    for (int d = 1; d < 256; d <<= 1) {
        int u = (t >= d) ? sh[t - d] : 0;
        __syncthreads();
        sh[t] += u;
        __syncthreads();
    }
    int boff = sh[blockIdx.x] - d_bsum[side][blockIdx.x];  // exclusive
    int i = blockIdx.x * 256 + t;
    if (i >= NA) return;
    if (side == 0) {
        int o = d_off_s[i] + boff;
        d_off_s[i] = o;
        d_cur_s[i] = o;
        d_rcs[i] = __fdividef(1.0f, fmaxf((float)d_icnt_s[i], 1.0f));
    } else {
        int o = d_off_h[i] + boff;
        d_off_h[i] = o;
        d_cur_h[i] = o;
        d_rch[i] = __fdividef(1.0f, fmaxf((float)d_icnt_h[i], 1.0f));
    }
}

__global__ void k_sort(const int* __restrict__ src, const int* __restrict__ hid,
                       const int* __restrict__ az) {
    int e = blockIdx.x * blockDim.x + threadIdx.x;
    if (e >= NI) return;
    int s = src[e];
    int h = hid[e];
    int z = __ldg(az + s);
    int ph = atomicAdd(&d_cur_h[h], 1);
    d_zA[ph] = (unsigned short)z;
    int ps = atomicAdd(&d_cur_s[s], 1);
    d_sB[ps] = ((unsigned)h << 16) | (unsigned)s;
}

// motif GEMM (attr only, K=96): [Mf|Mc] = attr @ W[128:222] + bias  (fork stream)
__global__ __launch_bounds__(256) void k_gemm_attr(const float* __restrict__ w_f,
                                                   const float* __restrict__ w_c,
                                                   const float* __restrict__ b_f,
                                                   const float* __restrict__ b_c,
                                                   const float* __restrict__ attr) {
    __shared__ float Wsm[KA * 128];   // 48 KB
    __shared__ float Xsm[64 * KA];    // 24 KB
    int t = threadIdx.x;
    int tx = t & 31;
    int ry = t >> 5;

    for (int idx = t; idx < KA * 128; idx += 256) {
        int k = idx >> 7, j = idx & 127;
        float v = 0.f;
        if (k < MD) v = (j < 64) ? w_f[(128 + k) * H + j] : w_c[(128 + k) * H + j - 64];
        Wsm[idx] = v;
    }
    int row0 = blockIdx.x * 64;
    for (int idx = t; idx < 64 * KA; idx += 256) {
        int r = idx / KA;
        int k = idx - r * KA;
        int row = row0 + r;
        float v = 0.f;
        if (row < NM && k < MD) v = attr[row * MD + k];
        Xsm[idx] = v;
    }
    __syncthreads();

    float acc[8][4];
#pragma unroll
    for (int r = 0; r < 8; r++)
#pragma unroll
        for (int c = 0; c < 4; c++) acc[r][c] = 0.f;

    for (int k0 = 0; k0 < KA; k0 += 4) {
        float4 wv[4];
#pragma unroll
        for (int i = 0; i < 4; i++)
            wv[i] = *reinterpret_cast<const float4*>(&Wsm[(k0 + i) * 128 + tx * 4]);
#pragma unroll
        for (int r = 0; r < 8; r++) {
            float4 xv = *reinterpret_cast<const float4*>(&Xsm[(ry * 8 + r) * KA + k0]);
            acc[r][0] = fmaf(xv.x, wv[0].x, acc[r][0]);
            acc[r][1] = fmaf(xv.x, wv[0].y, acc[r][1]);
            acc[r][2] = fmaf(xv.x, wv[0].z, acc[r][2]);
            acc[r][3] = fmaf(xv.x, wv[0].w, acc[r][3]);
            acc[r][0] = fmaf(xv.y, wv[1].x, acc[r][0]);
            acc[r][1] = fmaf(xv.y, wv[1].y, acc[r][1]);
            acc[r][2] = fmaf(xv.y, wv[1].z, acc[r][2]);
            acc[r][3] = fmaf(xv.y, wv[1].w, acc[r][3]);
            acc[r][0] = fmaf(xv.z, wv[2].x, acc[r][0]);
            acc[r][1] = fmaf(xv.z, wv[2].y, acc[r][1]);
            acc[r][2] = fmaf(xv.z, wv[2].z, acc[r][2]);
            acc[r][3] = fmaf(xv.z, wv[2].w, acc[r][3]);
            acc[r][0] = fmaf(xv.w, wv[3].x, acc[r][0]);
            acc[r][1] = fmaf(xv.w, wv[3].y, acc[r][1]);
            acc[r][2] = fmaf(xv.w, wv[3].z, acc[r][2]);
            acc[r][3] = fmaf(xv.w, wv[3].w, acc[r][3]);
        }
    }

    int col = tx * 4;
    float4 bias;
    if (col < 64) bias = *reinterpret_cast<const float4*>(&b_f[col]);
    else          bias = *reinterpret_cast<const float4*>(&b_c[col - 64]);
#pragma unroll
    for (int r = 0; r < 8; r++) {
        int row = row0 + ry * 8 + r;
        if (row < NM) {
            float4 o;
            o.x = acc[r][0] + bias.x; o.y = acc[r][1] + bias.y;
            o.z = acc[r][2] + bias.z; o.w = acc[r][3] + bias.w;
            if (col < 64) *reinterpret_cast<float4*>(&d_Mf[row * H + col]) = o;
            else          *reinterpret_cast<float4*>(&d_Mc[row * H + col - 64]) = o;
        }
    }
}

// phase A (after join): Mf/Mc[m] += (segment-sum of U[z]) * rch[m]
__global__ __launch_bounds__(256) void k_hxw2() {
    int m = blockIdx.x * 8 + (threadIdx.x >> 5);
    if (m >= NM) return;
    int q = (threadIdx.x & 31) << 2;
    int b = d_off_h[m], e = d_off_h[m + 1];
    float4 acc = make_float4(0.f, 0.f, 0.f, 0.f);
    int j = b;
    for (; j + 3 < e; j += 4) {
        int z0 = __ldg(d_zA + j), z1 = __ldg(d_zA + j + 1);
        int z2 = __ldg(d_zA + j + 2), z3 = __ldg(d_zA + j + 3);
        float4 v0 = __ldg((const float4*)(d_U + z0 * 128 + q));
        float4 v1 = __ldg((const float4*)(d_U + z1 * 128 + q));
        float4 v2 = __ldg((const float4*)(d_U + z2 * 128 + q));
        float4 v3 = __ldg((const float4*)(d_U + z3 * 128 + q));
        acc.x += (v0.x + v1.x) + (v2.x + v3.x);
        acc.y += (v0.y + v1.y) + (v2.y + v3.y);
        acc.z += (v0.z + v1.z) + (v2.z + v3.z);
        acc.w += (v0.w + v1.w) + (v2.w + v3.w);
    }
    for (; j < e; j++) {
        int z = __ldg(d_zA + j);
        float4 v = __ldg((const float4*)(d_U + z * 128 + q));
        acc.x += v.x; acc.y += v.y; acc.z += v.z; acc.w += v.w;
    }
    float rc = d_rch[m];
    float* dst = (q < 64) ? (d_Mf + m * H + q) : (d_Mc + m * H + (q - 64));
    float4 o = *reinterpret_cast<const float4*>(dst);
    o.x += acc.x * rc; o.y += acc.y * rc;
    o.z += acc.z * rc; o.w += acc.w * rc;
    *reinterpret_cast<float4*>(dst) = o;
}

// phase B: src-sorted chunks of CH=32; run-length register accumulation,
// red.v4 flush on atom change.
__global__ __launch_bounds__(256) void k_msg(const int* __restrict__ az) {
    int t = threadIdx.x;
    int grp = blockIdx.x * 16 + (t >> 4);
    if (grp >= NGRP) return;
    int q = (t & 15) << 2;
    int B = grp * CH;

    uint4 R[CH / 4];
#pragma unroll
    for (int i = 0; i < CH / 4; i++)
        R[i] = __ldg((const uint4*)(d_sB + B + i * 4));

    int cur = -1;
    float4 acc = make_float4(0.f, 0.f, 0.f, 0.f);
    float4 tf = acc, tc = acc;

#pragma unroll
    for (int i0 = 0; i0 < CH / 4; i0++) {
        unsigned rr[4] = {R[i0].x, R[i0].y, R[i0].z, R[i0].w};
        float4 mf[4], mc[4];
#pragma unroll
        for (int j = 0; j < 4; j++) {
            int m = (int)(rr[j] >> 16);
            mf[j] = __ldg((const float4*)(d_Mf + m * H + q));
            mc[j] = __ldg((const float4*)(d_Mc + m * H + q));
        }
#pragma unroll
        for (int j = 0; j < 4; j++) {
            int s = (int)(rr[j] & 0xFFFFu);
            if (s != cur) {
                if (cur >= 0) red_add_v4(&d_osum[cur * H + q], acc);
                cur = s;
                acc = make_float4(0.f, 0.f, 0.f, 0.f);
                int z = __ldg(az + s);
                tf = __ldg((const float4*)(d_Tf + z * H + q));
                tc = __ldg((const float4*)(d_Tc + z * H + q));
            }
            acc.x += gatef(tf.x + mf[j].x, tc.x + mc[j].x);
            acc.y += gatef(tf.y + mf[j].y, tc.y + mc[j].y);
            acc.z += gatef(tf.z + mf[j].z, tc.z + mc[j].z);
            acc.w += gatef(tf.w + mf[j].w, tc.w + mc[j].w);
        }
    }
    red_add_v4(&d_osum[cur * H + q], acc);
}

// BN statistics over out = osum * rcs
__global__ __launch_bounds__(256) void k_bnstats() {
    __shared__ float b1[64], b2[64];
    int t = threadIdx.x;
    if (t < 64) { b1[t] = 0.f; b2[t] = 0.f; }
    __syncthreads();
    int start = blockIdx.x * 256 + t;
    int q = (start & 15) << 2;
    float l1[4] = {0.f, 0.f, 0.f, 0.f};
    float l2[4] = {0.f, 0.f, 0.f, 0.f};
    for (int idx = start; idx < NA * 16; idx += 65536) {
        int i = idx >> 4;
        float rc = d_rcs[i];
        float4 o = *reinterpret_cast<const float4*>(&d_osum[i * H + q]);
        o.x *= rc; o.y *= rc; o.z *= rc; o.w *= rc;
        l1[0] += o.x; l2[0] += o.x * o.x;
        l1[1] += o.y; l2[1] += o.y * o.y;
        l1[2] += o.z; l2[2] += o.z * o.z;
        l1[3] += o.w; l2[3] += o.w * o.w;
    }
#pragma unroll
    for (int c = 0; c < 4; c++) {
        atomicAdd(&b1[q + c], l1[c]);
        atomicAdd(&b2[q + c], l2[c]);
    }
    __syncthreads();
    if (t < 64) {
        red_add_1(&d_bnsum[t], b1[t]);
        red_add_1(&d_bnsq[t], b2[t]);
    }
}

// normalize + residual + relu + pool
__global__ void k_final(const int* __restrict__ batch, const float* __restrict__ gamma,
                        const float* __restrict__ beta, const int* __restrict__ az,
                        const float* __restrict__ emb) {
    int tid = blockIdx.x * blockDim.x + threadIdx.x;
    if (tid >= NA * 16) return;
    int i = tid >> 4;
    int q = (tid & 15) << 2;
    int z = __ldg(az + i);
    float rc = d_rcs[i];
    float4 o = *reinterpret_cast<const float4*>(&d_osum[i * H + q]);
    float4 xv = __ldg((const float4*)(emb + z * H + q));
    float ov[4] = {o.x * rc, o.y * rc, o.z * rc, o.w * rc};
    float xr[4] = {xv.x, xv.y, xv.z, xv.w};
    float res[4];
#pragma unroll
    for (int c = 0; c < 4; c++) {
        int f = q + c;
        float mu = d_bnsum[f] * (1.0f / NA);
        float var = d_bnsq[f] * (1.0f / NA) - mu * mu;
        float inv = rsqrtf(var + BN_EPS);
        float v = (ov[c] - mu) * inv * gamma[f] + beta[f] + xr[c];
        res[c] = fmaxf(v, 0.f);
    }
    float4 r; r.x = res[0]; r.y = res[1]; r.z = res[2]; r.w = res[3];
    int g = __ldg(batch + i);
    red_add_v4(&d_gsum[g * H + q], r);
}

// MLP head (exact softplus kept here — 512 values only)
__global__ __launch_bounds__(128) void k_head(const float* __restrict__ w_l1,
                                              const float* __restrict__ b_l1,
                                              const float* __restrict__ w_out,
                                              const float* __restrict__ b_out,
                                              float* __restrict__ out) {
    __shared__ float gsm[64];
    __shared__ float red[128];
    int g = blockIdx.x;
    int t = threadIdx.x;
    if (t < 64) gsm[t] = d_gsum[g * H + t] * __fdividef(1.0f, fmaxf(d_gcnt[g], 1.0f));
    __syncthreads();
    float acc = b_l1[t];
#pragma unroll
    for (int f = 0; f < 64; f++)
        acc = fmaf(gsm[f], w_l1[f * HOUT + t], acc);
    float sp = lg2f(1.0f + ex2f(acc * L2E)) * LN2;
    red[t] = sp * w_out[t];
    __syncthreads();
    if (t < 64) red[t] += red[t + 64];
    __syncthreads();
    if (t < 32) {
        float s = red[t] + red[t + 32];
#pragma unroll
        for (int off = 16; off > 0; off >>= 1)
            s += __shfl_down_sync(0xffffffff, s, off);
        if (t == 0) out[g] = s + b_out[0];
    }
}

// ---------------- launch ----------------
extern "C" void kernel_launch(void* const* d_in, const int* in_sizes, int n_in,
                              void* d_out_p, int out_size) {
    const int*   atom_z = (const int*)d_in[0];
    const float* attr   = (const float*)d_in[1];
    const int*   hei    = (const int*)d_in[2];
    const int*   batch  = (const int*)d_in[3];
    const float* emb    = (const float*)d_in[4];
    const float* w_f    = (const float*)d_in[5];
    const float* b_f    = (const float*)d_in[6];
    const float* w_c    = (const float*)d_in[7];
    const float* b_c    = (const float*)d_in[8];
    const float* gamma  = (const float*)d_in[9];
    const float* beta   = (const float*)d_in[10];
    const float* w_l1   = (const float*)d_in[11];
    const float* b_l1   = (const float*)d_in[12];
    const float* w_out  = (const float*)d_in[13];
    const float* b_out  = (const float*)d_in[14];
    float* out = (float*)d_out_p;

    const int* src = hei;
    const int* hid = hei + NI;

    // Single auxiliary stream + 2 events (guard-proven R8 configuration).
    cudaStream_t s2;
    cudaEvent_t evF, evJ;
    cudaStreamCreateWithFlags(&s2, cudaStreamNonBlocking);
    cudaEventCreateWithFlags(&evF, cudaEventDisableTiming);
    cudaEventCreateWithFlags(&evJ, cudaEventDisableTiming);

    cudaEventRecord(evF, 0);
    cudaStreamWaitEvent(s2, evF, 0);
    k_tables<<<NZ, 256, 0, s2>>>(emb, w_f, w_c);
    k_gemm_attr<<<(NM + 63) / 64, 256, 0, s2>>>(w_f, w_c, b_f, b_c, attr);
    cudaEventRecord(evJ, s2);

    // origin: zero -> counts -> scan -> sort (exact R8 chain)
    k_zero<<<512, 256>>>();
    k_counts<<<(NI + 255) / 256, 256>>>(src, hid, batch);
    k_scan1<<<dim3(SCAN_BLOCKS, 2), 256>>>();
    k_scan23<<<dim3(SCAN_BLOCKS, 2), 256>>>();
    k_sort<<<(NI + 255) / 256, 256>>>(src, hid, atom_z);

    cudaStreamWaitEvent(0, evJ, 0);   // join: Mf/Mc + U ready
    k_hxw2<<<(NM + 7) / 8, 256>>>();
    k_msg<<<(NGRP + 15) / 16, 256>>>(atom_z);
    k_bnstats<<<256, 256>>>();
    k_final<<<(NA * 16 + 255) / 256, 256>>>(batch, gamma, beta, atom_z, emb);
    k_head<<<NG, 128>>>(w_l1, b_l1, w_out, b_out, out);
}

// round 17
// speedup vs baseline: 1.0539x; 1.0376x over previous
#include <cuda_runtime.h>

#define NA 50000
#define NM 50000
#define NI 600000
#define NG 512
#define H 64
#define MD 94
#define HOUT 128
#define KA 96             // attr K padded (94 -> 96)
#define NZ 101
#define BN_EPS 1e-5f
#define SCAN_BLOCKS 196   // ceil(50000/256)
#define NGRP (NI / 16)    // 37500

// ---------------- device scratch ----------------
__device__ __align__(256) float d_Tf[NZ * H];
__device__ __align__(256) float d_Tc[NZ * H];
__device__ __align__(256) float d_U[NZ * 128];    // emb @ W[64:128] (f|c halves)
__device__ __align__(256) float d_Mf[NM * H];
__device__ __align__(256) float d_Mc[NM * H];
__device__ __align__(256) float d_osum[NA * H];
__device__ float d_bnsum[H];
__device__ float d_bnsq[H];
__device__ __align__(256) float d_gsum[NG * H];
__device__ float d_gcnt[NG];
// sort machinery (both sides)
__device__ int d_icnt_s[NA];
__device__ int d_icnt_h[NM];
__device__ int d_off_s[NA + 1];
__device__ int d_off_h[NM + 1];
__device__ int d_cur_s[NA];
__device__ int d_cur_h[NM];
__device__ int d_bsum[2][256];    // padded to 256 (tail zero)
__device__ float d_rcs[NA];
__device__ float d_rch[NM];
__device__ __align__(16) unsigned short d_zA[NI];  // atom TYPE per incidence, hid-sorted
__device__ __align__(16) unsigned d_sB[NI];        // (h<<16)|s per incidence, src-sorted

// ---------------- fast math ----------------
__device__ __forceinline__ float ex2f(float x) { float r; asm("ex2.approx.ftz.f32 %0,%1;" : "=f"(r) : "f"(x)); return r; }
__device__ __forceinline__ float lg2f(float x) { float r; asm("lg2.approx.ftz.f32 %0,%1;" : "=f"(r) : "f"(x)); return r; }
__device__ __forceinline__ float rcpf(float x) { float r; asm("rcp.approx.ftz.f32 %0,%1;" : "=f"(r) : "f"(x)); return r; }
__device__ __forceinline__ float tanhf_a(float x) { float r; asm("tanh.approx.f32 %0,%1;" : "=f"(r) : "f"(x)); return r; }

#define L2E 1.4426950408889634f
#define LN2 0.6931471805599453f

// gate = sigmoid(a) * softplus(b); sigmoid via tanh.approx (3 MUFU total)
__device__ __forceinline__ float gatef(float a, float b) {
    float sg = fmaf(0.5f, tanhf_a(0.5f * a), 0.5f);
    float sp = lg2f(1.0f + ex2f(b * L2E)) * LN2;
    return sg * sp;
}

__device__ __forceinline__ void red_add_v4(float* p, float4 v) {
    asm volatile("red.global.add.v4.f32 [%0], {%1,%2,%3,%4};"
                 :: "l"(p), "f"(v.x), "f"(v.y), "f"(v.z), "f"(v.w) : "memory");
}
__device__ __forceinline__ void red_add_1(float* p, float v) {
    asm volatile("red.global.add.f32 [%0], %1;" :: "l"(p), "f"(v) : "memory");
}

// ---------------- kernels ----------------
__global__ void k_zero() {
    int tid = blockIdx.x * blockDim.x + threadIdx.x;
    int stride = gridDim.x * blockDim.x;
    for (int i = tid; i < NA * H; i += stride) d_osum[i] = 0.f;
    for (int i = tid; i < NA; i += stride) d_icnt_s[i] = 0;
    for (int i = tid; i < NM; i += stride) d_icnt_h[i] = 0;
    for (int i = tid; i < NG * H; i += stride) d_gsum[i] = 0.f;
    if (tid < NG) d_gcnt[tid] = 0.f;
    if (tid < H) { d_bnsum[tid] = 0.f; d_bnsq[tid] = 0.f; }
    if (tid < 256) { d_bsum[0][tid] = 0; d_bsum[1][tid] = 0; }
    if (tid == 0) { d_off_s[NA] = NI; d_off_h[NM] = NI; }
}

// tables: Tf/Tc = emb@W[:64] halves; U = emb@W[64:128] halves (101 x 128)
__global__ __launch_bounds__(256) void k_tables(const float* __restrict__ emb,
                                                const float* __restrict__ w_f,
                                                const float* __restrict__ w_c) {
    __shared__ float e[H];
    int z = blockIdx.x;
    int t = threadIdx.x;
    if (t < H) e[t] = emb[z * H + t];
    __syncthreads();
    float acc = 0.f;
    if (t < 64) {
#pragma unroll 8
        for (int k = 0; k < H; k++) acc = fmaf(e[k], w_f[k * H + t], acc);
        d_Tf[z * H + t] = acc;
    } else if (t < 128) {
        int j = t - 64;
#pragma unroll 8
        for (int k = 0; k < H; k++) acc = fmaf(e[k], w_c[k * H + j], acc);
        d_Tc[z * H + j] = acc;
    } else if (t < 192) {
        int j = t - 128;
#pragma unroll 8
        for (int k = 0; k < H; k++) acc = fmaf(e[k], w_f[(64 + k) * H + j], acc);
        d_U[z * 128 + j] = acc;
    } else {
        int j = t - 192;
#pragma unroll 8
        for (int k = 0; k < H; k++) acc = fmaf(e[k], w_c[(64 + k) * H + j], acc);
        d_U[z * 128 + 64 + j] = acc;
    }
}

// counts: incidence histograms only (gcnt moved to k_scan23)
__global__ void k_counts(const int* __restrict__ src, const int* __restrict__ hid) {
    int e = blockIdx.x * blockDim.x + threadIdx.x;
    if (e < NI) {
        atomicAdd(&d_icnt_s[src[e]], 1);
        atomicAdd(&d_icnt_h[hid[e]], 1);
    }
}

// pass 1: per-block inclusive scan, write local-exclusive offs + block sums
__global__ __launch_bounds__(256) void k_scan1() {
    __shared__ int sh[256];
    int side = blockIdx.y;
    const int* cnt = side ? d_icnt_h : d_icnt_s;
    int* off = side ? d_off_h : d_off_s;
    int t = threadIdx.x;
    int i = blockIdx.x * 256 + t;
    int v = (i < NA) ? cnt[i] : 0;
    sh[t] = v;
    __syncthreads();
#pragma unroll
    for (int d = 1; d < 256; d <<= 1) {
        int u = (t >= d) ? sh[t - d] : 0;
        __syncthreads();
        sh[t] += u;
        __syncthreads();
    }
    if (i < NA) off[i] = sh[t] - v;
    if (t == 255) d_bsum[side][blockIdx.x] = sh[255];
}

// pass 2+3 fused: each block re-scans block sums locally, applies offset.
// side 0 additionally accumulates the graph histogram (batch is per-atom).
__global__ __launch_bounds__(256) void k_scan23(const int* __restrict__ batch) {
    __shared__ int sh[256];
    int side = blockIdx.y;
    int t = threadIdx.x;
    int v = d_bsum[side][t];
    sh[t] = v;
    __syncthreads();
#pragma unroll
    for (int d = 1; d < 256; d <<= 1) {
        int u = (t >= d) ? sh[t - d] : 0;
        __syncthreads();
        sh[t] += u;
        __syncthreads();
    }
    int boff = sh[blockIdx.x] - d_bsum[side][blockIdx.x];  // exclusive
    int i = blockIdx.x * 256 + t;
    if (i >= NA) return;
    if (side == 0) {
        int o = d_off_s[i] + boff;
        d_off_s[i] = o;
        d_cur_s[i] = o;
        d_rcs[i] = __fdividef(1.0f, fmaxf((float)d_icnt_s[i], 1.0f));
        red_add_1(&d_gcnt[__ldg(batch + i)], 1.0f);
    } else {
        int o = d_off_h[i] + boff;
        d_off_h[i] = o;
        d_cur_h[i] = o;
        d_rch[i] = __fdividef(1.0f, fmaxf((float)d_icnt_h[i], 1.0f));
    }
}

__global__ void k_sort(const int* __restrict__ src, const int* __restrict__ hid,
                       const int* __restrict__ az) {
    int e = blockIdx.x * blockDim.x + threadIdx.x;
    if (e >= NI) return;
    int s = src[e];
    int h = hid[e];
    int z = __ldg(az + s);
    int ph = atomicAdd(&d_cur_h[h], 1);
    d_zA[ph] = (unsigned short)z;
    int ps = atomicAdd(&d_cur_s[s], 1);
    d_sB[ps] = ((unsigned)h << 16) | (unsigned)s;
}

// motif GEMM (attr only, K=96): [Mf|Mc] = attr @ W[128:222] + bias  (fork stream)
__global__ __launch_bounds__(256) void k_gemm_attr(const float* __restrict__ w_f,
                                                   const float* __restrict__ w_c,
                                                   const float* __restrict__ b_f,
                                                   const float* __restrict__ b_c,
                                                   const float* __restrict__ attr) {
    __shared__ float Wsm[KA * 128];   // 48 KB
    __shared__ float Xsm[64 * KA];    // 24 KB
    int t = threadIdx.x;
    int tx = t & 31;
    int ry = t >> 5;

    for (int idx = t; idx < KA * 128; idx += 256) {
        int k = idx >> 7, j = idx & 127;
        float v = 0.f;
        if (k < MD) v = (j < 64) ? w_f[(128 + k) * H + j] : w_c[(128 + k) * H + j - 64];
        Wsm[idx] = v;
    }
    int row0 = blockIdx.x * 64;
    for (int idx = t; idx < 64 * KA; idx += 256) {
        int r = idx / KA;
        int k = idx - r * KA;
        int row = row0 + r;
        float v = 0.f;
        if (row < NM && k < MD) v = attr[row * MD + k];
        Xsm[idx] = v;
    }
    __syncthreads();

    float acc[8][4];
#pragma unroll
    for (int r = 0; r < 8; r++)
#pragma unroll
        for (int c = 0; c < 4; c++) acc[r][c] = 0.f;

    for (int k0 = 0; k0 < KA; k0 += 4) {
        float4 wv[4];
#pragma unroll
        for (int i = 0; i < 4; i++)
            wv[i] = *reinterpret_cast<const float4*>(&Wsm[(k0 + i) * 128 + tx * 4]);
#pragma unroll
        for (int r = 0; r < 8; r++) {
            float4 xv = *reinterpret_cast<const float4*>(&Xsm[(ry * 8 + r) * KA + k0]);
            acc[r][0] = fmaf(xv.x, wv[0].x, acc[r][0]);
            acc[r][1] = fmaf(xv.x, wv[0].y, acc[r][1]);
            acc[r][2] = fmaf(xv.x, wv[0].z, acc[r][2]);
            acc[r][3] = fmaf(xv.x, wv[0].w, acc[r][3]);
            acc[r][0] = fmaf(xv.y, wv[1].x, acc[r][0]);
            acc[r][1] = fmaf(xv.y, wv[1].y, acc[r][1]);
            acc[r][2] = fmaf(xv.y, wv[1].z, acc[r][2]);
            acc[r][3] = fmaf(xv.y, wv[1].w, acc[r][3]);
            acc[r][0] = fmaf(xv.z, wv[2].x, acc[r][0]);
            acc[r][1] = fmaf(xv.z, wv[2].y, acc[r][1]);
            acc[r][2] = fmaf(xv.z, wv[2].z, acc[r][2]);
            acc[r][3] = fmaf(xv.z, wv[2].w, acc[r][3]);
            acc[r][0] = fmaf(xv.w, wv[3].x, acc[r][0]);
            acc[r][1] = fmaf(xv.w, wv[3].y, acc[r][1]);
            acc[r][2] = fmaf(xv.w, wv[3].z, acc[r][2]);
            acc[r][3] = fmaf(xv.w, wv[3].w, acc[r][3]);
        }
    }

    int col = tx * 4;
    float4 bias;
    if (col < 64) bias = *reinterpret_cast<const float4*>(&b_f[col]);
    else          bias = *reinterpret_cast<const float4*>(&b_c[col - 64]);
#pragma unroll
    for (int r = 0; r < 8; r++) {
        int row = row0 + ry * 8 + r;
        if (row < NM) {
            float4 o;
            o.x = acc[r][0] + bias.x; o.y = acc[r][1] + bias.y;
            o.z = acc[r][2] + bias.z; o.w = acc[r][3] + bias.w;
            if (col < 64) *reinterpret_cast<float4*>(&d_Mf[row * H + col]) = o;
            else          *reinterpret_cast<float4*>(&d_Mc[row * H + col - 64]) = o;
        }
    }
}

// phase A (after join): Mf/Mc[m] += (segment-sum of U[z]) * rch[m]
__global__ __launch_bounds__(256) void k_hxw2() {
    int m = blockIdx.x * 8 + (threadIdx.x >> 5);
    if (m >= NM) return;
    int q = (threadIdx.x & 31) << 2;
    int b = d_off_h[m], e = d_off_h[m + 1];
    float4 acc = make_float4(0.f, 0.f, 0.f, 0.f);
    int j = b;
    for (; j + 3 < e; j += 4) {
        int z0 = __ldg(d_zA + j), z1 = __ldg(d_zA + j + 1);
        int z2 = __ldg(d_zA + j + 2), z3 = __ldg(d_zA + j + 3);
        float4 v0 = __ldg((const float4*)(d_U + z0 * 128 + q));
        float4 v1 = __ldg((const float4*)(d_U + z1 * 128 + q));
        float4 v2 = __ldg((const float4*)(d_U + z2 * 128 + q));
        float4 v3 = __ldg((const float4*)(d_U + z3 * 128 + q));
        acc.x += (v0.x + v1.x) + (v2.x + v3.x);
        acc.y += (v0.y + v1.y) + (v2.y + v3.y);
        acc.z += (v0.z + v1.z) + (v2.z + v3.z);
        acc.w += (v0.w + v1.w) + (v2.w + v3.w);
    }
    for (; j < e; j++) {
        int z = __ldg(d_zA + j);
        float4 v = __ldg((const float4*)(d_U + z * 128 + q));
        acc.x += v.x; acc.y += v.y; acc.z += v.z; acc.w += v.w;
    }
    float rc = d_rch[m];
    float* dst = (q < 64) ? (d_Mf + m * H + q) : (d_Mc + m * H + (q - 64));
    float4 o = *reinterpret_cast<const float4*>(dst);
    o.x += acc.x * rc; o.y += acc.y * rc;
    o.z += acc.z * rc; o.w += acc.w * rc;
    *reinterpret_cast<float4*>(dst) = o;
}

// phase B: src-sorted chunks of 16; run-length register accumulation,
// red.v4 flush on atom change.
__global__ __launch_bounds__(256) void k_msg(const int* __restrict__ az) {
    int t = threadIdx.x;
    int grp = blockIdx.x * 16 + (t >> 4);
    if (grp >= NGRP) return;
    int q = (t & 15) << 2;
    int B = grp * 16;

    uint4 R[4];
#pragma unroll
    for (int i = 0; i < 4; i++)
        R[i] = __ldg((const uint4*)(d_sB + B + i * 4));

    int cur = -1;
    float4 acc = make_float4(0.f, 0.f, 0.f, 0.f);
    float4 tf = acc, tc = acc;

#pragma unroll
    for (int i0 = 0; i0 < 4; i0++) {
        unsigned rr[4] = {R[i0].x, R[i0].y, R[i0].z, R[i0].w};
        float4 mf[4], mc[4];
#pragma unroll
        for (int j = 0; j < 4; j++) {
            int m = (int)(rr[j] >> 16);
            mf[j] = __ldg((const float4*)(d_Mf + m * H + q));
            mc[j] = __ldg((const float4*)(d_Mc + m * H + q));
        }
#pragma unroll
        for (int j = 0; j < 4; j++) {
            int s = (int)(rr[j] & 0xFFFFu);
            if (s != cur) {
                if (cur >= 0) red_add_v4(&d_osum[cur * H + q], acc);
                cur = s;
                acc = make_float4(0.f, 0.f, 0.f, 0.f);
                int z = __ldg(az + s);
                tf = __ldg((const float4*)(d_Tf + z * H + q));
                tc = __ldg((const float4*)(d_Tc + z * H + q));
            }
            acc.x += gatef(tf.x + mf[j].x, tc.x + mc[j].x);
            acc.y += gatef(tf.y + mf[j].y, tc.y + mc[j].y);
            acc.z += gatef(tf.z + mf[j].z, tc.z + mc[j].z);
            acc.w += gatef(tf.w + mf[j].w, tc.w + mc[j].w);
        }
    }
    red_add_v4(&d_osum[cur * H + q], acc);
}

// BN statistics over out = osum * rcs
__global__ __launch_bounds__(256) void k_bnstats() {
    __shared__ float b1[64], b2[64];
    int t = threadIdx.x;
    if (t < 64) { b1[t] = 0.f; b2[t] = 0.f; }
    __syncthreads();
    int start = blockIdx.x * 256 + t;
    int q = (start & 15) << 2;
    float l1[4] = {0.f, 0.f, 0.f, 0.f};
    float l2[4] = {0.f, 0.f, 0.f, 0.f};
    for (int idx = start; idx < NA * 16; idx += 65536) {
        int i = idx >> 4;
        float rc = d_rcs[i];
        float4 o = *reinterpret_cast<const float4*>(&d_osum[i * H + q]);
        o.x *= rc; o.y *= rc; o.z *= rc; o.w *= rc;
        l1[0] += o.x; l2[0] += o.x * o.x;
        l1[1] += o.y; l2[1] += o.y * o.y;
        l1[2] += o.z; l2[2] += o.z * o.z;
        l1[3] += o.w; l2[3] += o.w * o.w;
    }
#pragma unroll
    for (int c = 0; c < 4; c++) {
        atomicAdd(&b1[q + c], l1[c]);
        atomicAdd(&b2[q + c], l2[c]);
    }
    __syncthreads();
    if (t < 64) {
        red_add_1(&d_bnsum[t], b1[t]);
        red_add_1(&d_bnsq[t], b2[t]);
    }
}

// normalize + residual + relu + pool
__global__ void k_final(const int* __restrict__ batch, const float* __restrict__ gamma,
                        const float* __restrict__ beta, const int* __restrict__ az,
                        const float* __restrict__ emb) {
    int tid = blockIdx.x * blockDim.x + threadIdx.x;
    if (tid >= NA * 16) return;
    int i = tid >> 4;
    int q = (tid & 15) << 2;
    int z = __ldg(az + i);
    float rc = d_rcs[i];
    float4 o = *reinterpret_cast<const float4*>(&d_osum[i * H + q]);
    float4 xv = __ldg((const float4*)(emb + z * H + q));
    float ov[4] = {o.x * rc, o.y * rc, o.z * rc, o.w * rc};
    float xr[4] = {xv.x, xv.y, xv.z, xv.w};
    float res[4];
#pragma unroll
    for (int c = 0; c < 4; c++) {
        int f = q + c;
        float mu = d_bnsum[f] * (1.0f / NA);
        float var = d_bnsq[f] * (1.0f / NA) - mu * mu;
        float inv = rsqrtf(var + BN_EPS);
        float v = (ov[c] - mu) * inv * gamma[f] + beta[f] + xr[c];
        res[c] = fmaxf(v, 0.f);
    }
    float4 r; r.x = res[0]; r.y = res[1]; r.z = res[2]; r.w = res[3];
    int g = __ldg(batch + i);
    red_add_v4(&d_gsum[g * H + q], r);
}

// MLP head (exact softplus kept here — 512 values only)
__global__ __launch_bounds__(128) void k_head(const float* __restrict__ w_l1,
                                              const float* __restrict__ b_l1,
                                              const float* __restrict__ w_out,
                                              const float* __restrict__ b_out,
                                              float* __restrict__ out) {
    __shared__ float gsm[64];
    __shared__ float red[128];
    int g = blockIdx.x;
    int t = threadIdx.x;
    if (t < 64) gsm[t] = d_gsum[g * H + t] * __fdividef(1.0f, fmaxf(d_gcnt[g], 1.0f));
    __syncthreads();
    float acc = b_l1[t];
#pragma unroll
    for (int f = 0; f < 64; f++)
        acc = fmaf(gsm[f], w_l1[f * HOUT + t], acc);
    float sp = lg2f(1.0f + ex2f(acc * L2E)) * LN2;
    red[t] = sp * w_out[t];
    __syncthreads();
    if (t < 64) red[t] += red[t + 64];
    __syncthreads();
    if (t < 32) {
        float s = red[t] + red[t + 32];
#pragma unroll
        for (int off = 16; off > 0; off >>= 1)
            s += __shfl_down_sync(0xffffffff, s, off);
        if (t == 0) out[g] = s + b_out[0];
    }
}

// ---------------- launch ----------------
extern "C" void kernel_launch(void* const* d_in, const int* in_sizes, int n_in,
                              void* d_out_p, int out_size) {
    const int*   atom_z = (const int*)d_in[0];
    const float* attr   = (const float*)d_in[1];
    const int*   hei    = (const int*)d_in[2];
    const int*   batch  = (const int*)d_in[3];
    const float* emb    = (const float*)d_in[4];
    const float* w_f    = (const float*)d_in[5];
    const float* b_f    = (const float*)d_in[6];
    const float* w_c    = (const float*)d_in[7];
    const float* b_c    = (const float*)d_in[8];
    const float* gamma  = (const float*)d_in[9];
    const float* beta   = (const float*)d_in[10];
    const float* w_l1   = (const float*)d_in[11];
    const float* b_l1   = (const float*)d_in[12];
    const float* w_out  = (const float*)d_in[13];
    const float* b_out  = (const float*)d_in[14];
    float* out = (float*)d_out_p;

    const int* src = hei;
    const int* hid = hei + NI;

    // Single auxiliary stream + 2 events (guard-proven R8 configuration).
    cudaStream_t s2;
    cudaEvent_t evF, evJ;
    cudaStreamCreateWithFlags(&s2, cudaStreamNonBlocking);
    cudaEventCreateWithFlags(&evF, cudaEventDisableTiming);
    cudaEventCreateWithFlags(&evJ, cudaEventDisableTiming);

    cudaEventRecord(evF, 0);
    cudaStreamWaitEvent(s2, evF, 0);
    k_tables<<<NZ, 256, 0, s2>>>(emb, w_f, w_c);
    k_gemm_attr<<<(NM + 63) / 64, 256, 0, s2>>>(w_f, w_c, b_f, b_c, attr);
    cudaEventRecord(evJ, s2);

    // origin: zero -> counts -> scan -> sort (R14 chain; gcnt moved to scan23)
    k_zero<<<512, 256>>>();
    k_counts<<<(NI + 255) / 256, 256>>>(src, hid);
    k_scan1<<<dim3(SCAN_BLOCKS, 2), 256>>>();
    k_scan23<<<dim3(SCAN_BLOCKS, 2), 256>>>(batch);
    k_sort<<<(NI + 255) / 256, 256>>>(src, hid, atom_z);

    cudaStreamWaitEvent(0, evJ, 0);   // join: Mf/Mc + U ready
    k_hxw2<<<(NM + 7) / 8, 256>>>();
    k_msg<<<(NGRP + 15) / 16, 256>>>(atom_z);
    k_bnstats<<<256, 256>>>();
    k_final<<<(NA * 16 + 255) / 256, 256>>>(batch, gamma, beta, atom_z, emb);
    k_head<<<NG, 128>>>(w_l1, b_l1, w_out, b_out, out);
}